// round 1
// baseline (speedup 1.0000x reference)
#include <cuda_runtime.h>
#include <math.h>

// Fixed problem shape (see reference): T=4096, C=2048, N_FEAT=2048
#define T_DIM 4096
#define C_DIM 2048
#define NF_DIM 2048
#define QKV_N (3 * NF_DIM)   // 6144

// Scratch (allocation-free rule: __device__ globals).
// g_qkv: (T, 3*NF) fp32 = 96 MB ; g_att: (T, T) fp32 = 64 MB (att, then p in-place)
__device__ float g_qkv[(size_t)T_DIM * QKV_N];
__device__ float g_att[(size_t)T_DIM * T_DIM];

// ---------------------------------------------------------------------------
// Kernel 1: qkv = x @ W + b        (M=4096, N=6144, K=2048)  A row-major K-contig,
//                                   B row-major N-contig ("NN"), bias epilogue.
// 128x128 tile, BK=8, 256 threads, 8x8 per-thread microtile.
// ---------------------------------------------------------------------------
__global__ __launch_bounds__(256)
void qkv_gemm_kernel(const float* __restrict__ A, const float* __restrict__ B,
                     const float* __restrict__ bias)
{
    const int K = C_DIM;
    const int N = QKV_N;
    __shared__ float As[8][128];
    __shared__ float Bs[8][128];

    const int tid = threadIdx.x;
    const int m0 = blockIdx.y * 128;
    const int n0 = blockIdx.x * 128;

    const int arow = tid >> 1;            // 0..127
    const int acol = (tid & 1) << 2;      // 0 or 4
    const int brow = tid >> 5;            // 0..7
    const int bcol = (tid & 31) << 2;     // 0..124

    const float* Ap = A + (size_t)(m0 + arow) * K + acol;
    const float* Bp = B + (size_t)brow * N + n0 + bcol;

    float acc[8][8];
#pragma unroll
    for (int i = 0; i < 8; i++)
#pragma unroll
        for (int j = 0; j < 8; j++) acc[i][j] = 0.f;

    const int tx = (tid & 15) << 3;   // output col offset in tile
    const int ty = (tid >> 4) << 3;   // output row offset in tile

    for (int k0 = 0; k0 < K; k0 += 8) {
        float4 av = *(const float4*)(Ap + k0);
        float4 bv = *(const float4*)(Bp + (size_t)k0 * N);
        As[acol + 0][arow] = av.x;
        As[acol + 1][arow] = av.y;
        As[acol + 2][arow] = av.z;
        As[acol + 3][arow] = av.w;
        *(float4*)&Bs[brow][bcol] = bv;
        __syncthreads();
#pragma unroll
        for (int kk = 0; kk < 8; kk++) {
            float a[8], bb[8];
#pragma unroll
            for (int i = 0; i < 8; i++) a[i] = As[kk][ty + i];
#pragma unroll
            for (int j = 0; j < 8; j++) bb[j] = Bs[kk][tx + j];
#pragma unroll
            for (int i = 0; i < 8; i++)
#pragma unroll
                for (int j = 0; j < 8; j++)
                    acc[i][j] = fmaf(a[i], bb[j], acc[i][j]);
        }
        __syncthreads();
    }

#pragma unroll
    for (int i = 0; i < 8; i++) {
        size_t outb = (size_t)(m0 + ty + i) * N + n0 + tx;
#pragma unroll
        for (int j = 0; j < 8; j += 4) {
            float4 r;
            r.x = acc[i][j + 0] + bias[n0 + tx + j + 0];
            r.y = acc[i][j + 1] + bias[n0 + tx + j + 1];
            r.z = acc[i][j + 2] + bias[n0 + tx + j + 2];
            r.w = acc[i][j + 3] + bias[n0 + tx + j + 3];
            *(float4*)&g_qkv[outb + j] = r;
        }
    }
}

// ---------------------------------------------------------------------------
// Kernel 2: att = (q @ k^T) * scale    (M=N=4096, K=2048) "NT" layout.
// Only lower-triangular blocks (jb <= ib) and blocks not fully inside the
// left/top padding are computed; everything else is never read by softmax.
// ---------------------------------------------------------------------------
__global__ __launch_bounds__(256)
void s_gemm_kernel(const int* __restrict__ npadd_ptr)
{
    const int ib = blockIdx.y;
    const int jb = blockIdx.x;
    if (jb > ib) return;                         // causal block skip
    const int np = *npadd_ptr;
    if ((jb + 1) * 128 <= np) return;            // all cols padded
    if ((ib + 1) * 128 <= np) return;            // all rows padded

    const int K = NF_DIM;
    const int lda = QKV_N;
    const float* A = g_qkv;            // q
    const float* B = g_qkv + NF_DIM;   // k
    __shared__ float As[8][128];
    __shared__ float Bs[8][128];

    const int tid = threadIdx.x;
    const int m0 = ib * 128;
    const int n0 = jb * 128;

    const int arow = tid >> 1;
    const int acol = (tid & 1) << 2;

    const float* Ap = A + (size_t)(m0 + arow) * lda + acol;
    const float* Bp = B + (size_t)(n0 + arow) * lda + acol;

    float acc[8][8];
#pragma unroll
    for (int i = 0; i < 8; i++)
#pragma unroll
        for (int j = 0; j < 8; j++) acc[i][j] = 0.f;

    const int tx = (tid & 15) << 3;
    const int ty = (tid >> 4) << 3;

    for (int k0 = 0; k0 < K; k0 += 8) {
        float4 av = *(const float4*)(Ap + k0);
        float4 bv = *(const float4*)(Bp + k0);
        As[acol + 0][arow] = av.x;
        As[acol + 1][arow] = av.y;
        As[acol + 2][arow] = av.z;
        As[acol + 3][arow] = av.w;
        Bs[acol + 0][arow] = bv.x;
        Bs[acol + 1][arow] = bv.y;
        Bs[acol + 2][arow] = bv.z;
        Bs[acol + 3][arow] = bv.w;
        __syncthreads();
#pragma unroll
        for (int kk = 0; kk < 8; kk++) {
            float a[8], bb[8];
#pragma unroll
            for (int i = 0; i < 8; i++) a[i] = As[kk][ty + i];
#pragma unroll
            for (int j = 0; j < 8; j++) bb[j] = Bs[kk][tx + j];
#pragma unroll
            for (int i = 0; i < 8; i++)
#pragma unroll
                for (int j = 0; j < 8; j++)
                    acc[i][j] = fmaf(a[i], bb[j], acc[i][j]);
        }
        __syncthreads();
    }

    const float scale = 0.02209708691207961f;  // 1/sqrt(2048)
#pragma unroll
    for (int i = 0; i < 8; i++) {
        size_t outb = (size_t)(m0 + ty + i) * T_DIM + n0 + tx;
#pragma unroll
        for (int j = 0; j < 8; j += 4) {
            float4 r;
            r.x = acc[i][j + 0] * scale;
            r.y = acc[i][j + 1] * scale;
            r.z = acc[i][j + 2] * scale;
            r.w = acc[i][j + 3] * scale;
            *(float4*)&g_att[outb + j] = r;
        }
    }
}

// ---------------------------------------------------------------------------
// Kernel 3: row softmax over att, in place -> p.
// Valid window for row i (i >= np) is j in [np, i]; everything else written 0.
// Rows i < np are written fully 0 (reference zeroes padding rows).
// One block per row.
// ---------------------------------------------------------------------------
__global__ __launch_bounds__(256)
void softmax_kernel(const int* __restrict__ npadd_ptr)
{
    const int i = blockIdx.x;
    const int tid = threadIdx.x;
    const int np = *npadd_ptr;
    float* row = g_att + (size_t)i * T_DIM;
    __shared__ float red[256];

    if (i < np) {
        for (int j = tid; j < T_DIM; j += 256) row[j] = 0.f;
        return;
    }

    // pass 1: max over [np, i]
    float m = -3.402823466e+38f;
    for (int j = np + tid; j <= i; j += 256) m = fmaxf(m, row[j]);
    red[tid] = m;
    __syncthreads();
    for (int s = 128; s > 0; s >>= 1) {
        if (tid < s) red[tid] = fmaxf(red[tid], red[tid + s]);
        __syncthreads();
    }
    const float rowmax = red[0];
    __syncthreads();

    // pass 2: sum of exp
    float ssum = 0.f;
    for (int j = np + tid; j <= i; j += 256) ssum += __expf(row[j] - rowmax);
    red[tid] = ssum;
    __syncthreads();
    for (int s = 128; s > 0; s >>= 1) {
        if (tid < s) red[tid] += red[tid + s];
        __syncthreads();
    }
    const float inv = 1.0f / red[0];

    // pass 3: write normalized probs, exact zeros outside the valid window
    for (int j = tid; j < T_DIM; j += 256) {
        float v = 0.f;
        if (j >= np && j <= i) v = __expf(row[j] - rowmax) * inv;
        row[j] = v;
    }
}

// ---------------------------------------------------------------------------
// Kernel 4: y = p @ v              (M=4096, N=2048, K truncated per row-block)
// p is exactly zero for j > i and j < np, so the K loop runs over
// [floor(np/128)*128, (ib+1)*128). Row blocks fully inside padding produce 0.
// ---------------------------------------------------------------------------
__global__ __launch_bounds__(256)
void y_gemm_kernel(float* __restrict__ Y, const int* __restrict__ npadd_ptr)
{
    const int ib = blockIdx.y;
    const int m0 = ib * 128;
    const int n0 = blockIdx.x * 128;
    const int np = *npadd_ptr;
    const int kstart = (np >> 7) << 7;
    const int kmax = (ib + 1) * 128;

    const float* A = g_att;                 // p, lda = T_DIM
    const float* B = g_qkv + 2 * NF_DIM;    // v, ldb = QKV_N
    __shared__ float As[8][128];
    __shared__ float Bs[8][128];

    const int tid = threadIdx.x;
    const int arow = tid >> 1;
    const int acol = (tid & 1) << 2;
    const int brow = tid >> 5;
    const int bcol = (tid & 31) << 2;

    const float* Ap = A + (size_t)(m0 + arow) * T_DIM + acol;
    const float* Bp = B + (size_t)brow * QKV_N + n0 + bcol;

    float acc[8][8];
#pragma unroll
    for (int i = 0; i < 8; i++)
#pragma unroll
        for (int j = 0; j < 8; j++) acc[i][j] = 0.f;

    const int tx = (tid & 15) << 3;
    const int ty = (tid >> 4) << 3;

    for (int k0 = kstart; k0 < kmax; k0 += 8) {
        float4 av = *(const float4*)(Ap + k0);
        float4 bv = *(const float4*)(Bp + (size_t)k0 * QKV_N);
        As[acol + 0][arow] = av.x;
        As[acol + 1][arow] = av.y;
        As[acol + 2][arow] = av.z;
        As[acol + 3][arow] = av.w;
        *(float4*)&Bs[brow][bcol] = bv;
        __syncthreads();
#pragma unroll
        for (int kk = 0; kk < 8; kk++) {
            float a[8], bb[8];
#pragma unroll
            for (int i = 0; i < 8; i++) a[i] = As[kk][ty + i];
#pragma unroll
            for (int j = 0; j < 8; j++) bb[j] = Bs[kk][tx + j];
#pragma unroll
            for (int i = 0; i < 8; i++)
#pragma unroll
                for (int j = 0; j < 8; j++)
                    acc[i][j] = fmaf(a[i], bb[j], acc[i][j]);
        }
        __syncthreads();
    }

#pragma unroll
    for (int i = 0; i < 8; i++) {
        size_t outb = (size_t)(m0 + ty + i) * NF_DIM + n0 + tx;
#pragma unroll
        for (int j = 0; j < 8; j += 4) {
            float4 r;
            r.x = acc[i][j + 0];
            r.y = acc[i][j + 1];
            r.z = acc[i][j + 2];
            r.w = acc[i][j + 3];
            *(float4*)&Y[outb + j] = r;
        }
    }
}

// ---------------------------------------------------------------------------
extern "C" void kernel_launch(void* const* d_in, const int* in_sizes, int n_in,
                              void* d_out, int out_size)
{
    const float* x  = (const float*)d_in[0];   // (4096, 2048)
    const float* W  = (const float*)d_in[1];   // (2048, 6144)
    const float* b  = (const float*)d_in[2];   // (6144,)
    const int* npad = (const int*)d_in[3];     // scalar on device
    float* y = (float*)d_out;                  // (4096, 2048)

    (void)in_sizes; (void)n_in; (void)out_size;

    qkv_gemm_kernel<<<dim3(QKV_N / 128, T_DIM / 128), 256>>>(x, W, b);
    s_gemm_kernel<<<dim3(T_DIM / 128, T_DIM / 128), 256>>>(npad);
    softmax_kernel<<<T_DIM, 256>>>(npad);
    y_gemm_kernel<<<dim3(NF_DIM / 128, T_DIM / 128), 256>>>(y, npad);
}

// round 9
// speedup vs baseline: 2.2160x; 2.2160x over previous
#include <cuda_runtime.h>
#include <cuda_fp16.h>
#include <mma.h>
#include <stdint.h>

using namespace nvcuda;

#define T_DIM 4096
#define C_DIM 2048
#define NF_DIM 2048
#define QKV_N 6144
#define SA 40   // SMEM row stride (halves): 80B, multiple of 16B, conflict-light

// ---------------------------------------------------------------------------
// Scratch (__device__ globals; allocation-free rule)
// ---------------------------------------------------------------------------
__device__ float g_qkv[(size_t)T_DIM * QKV_N];        // raw qkv (fp32, no bias)
__device__ float g_att[(size_t)T_DIM * T_DIM];        // raw scores (unscaled)
__device__ __half g_xhi[(size_t)T_DIM * C_DIM];
__device__ __half g_xlo[(size_t)T_DIM * C_DIM];
__device__ __half g_WThi[(size_t)QKV_N * C_DIM];      // W^T : [6144][2048]
__device__ __half g_WTlo[(size_t)QKV_N * C_DIM];
__device__ __half g_qhi[(size_t)T_DIM * NF_DIM];
__device__ __half g_qlo[(size_t)T_DIM * NF_DIM];
__device__ __half g_khi[(size_t)T_DIM * NF_DIM];
__device__ __half g_klo[(size_t)T_DIM * NF_DIM];
__device__ __half g_vThi[(size_t)NF_DIM * T_DIM];     // v^T : [2048][4096]
__device__ __half g_vTlo[(size_t)NF_DIM * T_DIM];
__device__ __half g_phi[(size_t)T_DIM * T_DIM];
__device__ __half g_plo[(size_t)T_DIM * T_DIM];

typedef wmma::fragment<wmma::accumulator, 16, 16, 16, float> AccFrag;
typedef wmma::fragment<wmma::matrix_a, 16, 16, 16, __half, wmma::row_major> AFrag;
typedef wmma::fragment<wmma::matrix_b, 16, 16, 16, __half, wmma::col_major> BFrag;

// ---------------------------------------------------------------------------
// Core: C(128x64) += A(128xK) * B(64xK)^T, fp16 hi/lo 3-pass compensation.
// 256 threads = 8 warps, warp grid 4(m) x 2(n), warp tile 32x32 (2x2 wmma).
// All fragment traffic via wmma API (compiler-managed).
// ---------------------------------------------------------------------------
__device__ __forceinline__ void mm_core(
    const __half* __restrict__ Ahi, const __half* __restrict__ Alo,
    int m0, int lda,
    const __half* __restrict__ Bhi, const __half* __restrict__ Blo,
    int n0, int ldb,
    int kstart, int kend, AccFrag acc[2][2])
{
    __shared__ __align__(16) __half As[2][128][SA];
    __shared__ __align__(16) __half Bs[2][64][SA];
    const int tid = threadIdx.x;
    const int wid = tid >> 5;
    const int warp_m = (wid >> 1) * 32;
    const int warp_n = (wid & 1) * 32;

    const int lrow = tid >> 2;         // gmem load row (0..63)
    const int lq = (tid & 3) * 8;      // gmem load col quad (0,8,16,24)

    for (int kc = kstart; kc < kend; kc += 32) {
#pragma unroll
        for (int it = 0; it < 2; it++) {
            int row = lrow + it * 64;
            *(uint4*)&As[0][row][lq] =
                *(const uint4*)(Ahi + (size_t)(m0 + row) * lda + kc + lq);
            *(uint4*)&As[1][row][lq] =
                *(const uint4*)(Alo + (size_t)(m0 + row) * lda + kc + lq);
        }
        *(uint4*)&Bs[0][lrow][lq] =
            *(const uint4*)(Bhi + (size_t)(n0 + lrow) * ldb + kc + lq);
        *(uint4*)&Bs[1][lrow][lq] =
            *(const uint4*)(Blo + (size_t)(n0 + lrow) * ldb + kc + lq);
        __syncthreads();

#pragma unroll
        for (int ks = 0; ks < 32; ks += 16) {
            AFrag a_hi[2], a_lo[2];
#pragma unroll
            for (int mt = 0; mt < 2; mt++) {
                wmma::load_matrix_sync(a_hi[mt], &As[0][warp_m + mt * 16][ks], SA);
                wmma::load_matrix_sync(a_lo[mt], &As[1][warp_m + mt * 16][ks], SA);
            }
#pragma unroll
            for (int nt = 0; nt < 2; nt++) {
                BFrag b_hi, b_lo;
                wmma::load_matrix_sync(b_hi, &Bs[0][warp_n + nt * 16][ks], SA);
                wmma::load_matrix_sync(b_lo, &Bs[1][warp_n + nt * 16][ks], SA);
#pragma unroll
                for (int mt = 0; mt < 2; mt++) {
                    wmma::mma_sync(acc[mt][nt], a_hi[mt], b_hi, acc[mt][nt]);
                    wmma::mma_sync(acc[mt][nt], a_hi[mt], b_lo, acc[mt][nt]);
                    wmma::mma_sync(acc[mt][nt], a_lo[mt], b_hi, acc[mt][nt]);
                }
            }
        }
        __syncthreads();
    }
}

// ---------------------------------------------------------------------------
// GEMM 1: raw qkv = x @ W  (bias added later).  Store fp32 via wmma.
// ---------------------------------------------------------------------------
__global__ void __launch_bounds__(256, 2) qkv_mm() {
    AccFrag acc[2][2];
#pragma unroll
    for (int mt = 0; mt < 2; mt++)
#pragma unroll
        for (int nt = 0; nt < 2; nt++) wmma::fill_fragment(acc[mt][nt], 0.f);

    const int m0 = blockIdx.y * 128, n0 = blockIdx.x * 64;
    mm_core(g_xhi, g_xlo, m0, C_DIM, g_WThi, g_WTlo, n0, C_DIM, 0, C_DIM, acc);

    const int wid = threadIdx.x >> 5;
    const int warp_m = (wid >> 1) * 32, warp_n = (wid & 1) * 32;
#pragma unroll
    for (int mt = 0; mt < 2; mt++)
#pragma unroll
        for (int nt = 0; nt < 2; nt++)
            wmma::store_matrix_sync(
                g_qkv + (size_t)(m0 + warp_m + mt * 16) * QKV_N + n0 + warp_n + nt * 16,
                acc[mt][nt], QKV_N, wmma::mem_row_major);
}

// ---------------------------------------------------------------------------
// GEMM 2: raw att = q @ k^T  (scale folded into softmax)
// ---------------------------------------------------------------------------
__global__ void __launch_bounds__(256, 2) s_mm(const int* __restrict__ npadd_ptr) {
    const int ib = blockIdx.y, jb = blockIdx.x;
    if (jb * 64 >= (ib + 1) * 128) return;     // fully above diagonal
    const int np = *npadd_ptr;
    if ((jb + 1) * 64 <= np) return;           // all cols padded
    if ((ib + 1) * 128 <= np) return;          // all rows padded

    AccFrag acc[2][2];
#pragma unroll
    for (int mt = 0; mt < 2; mt++)
#pragma unroll
        for (int nt = 0; nt < 2; nt++) wmma::fill_fragment(acc[mt][nt], 0.f);

    const int m0 = ib * 128, n0 = jb * 64;
    mm_core(g_qhi, g_qlo, m0, NF_DIM, g_khi, g_klo, n0, NF_DIM, 0, NF_DIM, acc);

    const int wid = threadIdx.x >> 5;
    const int warp_m = (wid >> 1) * 32, warp_n = (wid & 1) * 32;
#pragma unroll
    for (int mt = 0; mt < 2; mt++)
#pragma unroll
        for (int nt = 0; nt < 2; nt++)
            wmma::store_matrix_sync(
                g_att + (size_t)(m0 + warp_m + mt * 16) * T_DIM + n0 + warp_n + nt * 16,
                acc[mt][nt], T_DIM, wmma::mem_row_major);
}

// ---------------------------------------------------------------------------
// GEMM 3: y = p @ v  (K truncated at diagonal / padding), store direct to out.
// ---------------------------------------------------------------------------
__global__ void __launch_bounds__(256, 2) y_mm(float* __restrict__ Y,
                                               const int* __restrict__ npadd_ptr) {
    const int ib = blockIdx.y;
    const int m0 = ib * 128, n0 = blockIdx.x * 64;
    const int np = *npadd_ptr;
    const int kstart = (np >> 5) << 5;
    const int kend = (ib + 1) * 128;

    if (kstart >= kend) {  // fully padded row block -> zeros
        const int tid = threadIdx.x;
        for (int e = tid; e < 128 * 64; e += 256) {
            int r = e >> 6, c = e & 63;
            Y[(size_t)(m0 + r) * NF_DIM + n0 + c] = 0.f;
        }
        return;
    }

    AccFrag acc[2][2];
#pragma unroll
    for (int mt = 0; mt < 2; mt++)
#pragma unroll
        for (int nt = 0; nt < 2; nt++) wmma::fill_fragment(acc[mt][nt], 0.f);

    mm_core(g_phi, g_plo, m0, T_DIM, g_vThi, g_vTlo, n0, T_DIM, kstart, kend, acc);

    const int wid = threadIdx.x >> 5;
    const int warp_m = (wid >> 1) * 32, warp_n = (wid & 1) * 32;
#pragma unroll
    for (int mt = 0; mt < 2; mt++)
#pragma unroll
        for (int nt = 0; nt < 2; nt++)
            wmma::store_matrix_sync(
                Y + (size_t)(m0 + warp_m + mt * 16) * NF_DIM + n0 + warp_n + nt * 16,
                acc[mt][nt], NF_DIM, wmma::mem_row_major);
}

// ---------------------------------------------------------------------------
// Prep kernels
// ---------------------------------------------------------------------------
__global__ void __launch_bounds__(256) split_x_kernel(const float* __restrict__ x) {
    size_t i = ((size_t)blockIdx.x * 256 + threadIdx.x) * 4;
    float4 v = *(const float4*)(x + i);
    float f[4] = {v.x, v.y, v.z, v.w};
    __half h[4], l[4];
#pragma unroll
    for (int e = 0; e < 4; e++) {
        h[e] = __float2half(f[e]);
        l[e] = __float2half(f[e] - __half2float(h[e]));
    }
    *(uint2*)(g_xhi + i) = *(const uint2*)h;
    *(uint2*)(g_xlo + i) = *(const uint2*)l;
}

// W^T split: dst[col][row] = split(W[row][col])
__global__ void __launch_bounds__(256) transpose_split_W(const float* __restrict__ W) {
    __shared__ float t[32][33];
    const int tx = threadIdx.x, ty = threadIdx.y;  // 32 x 8
    const int bx = blockIdx.x * 32, by = blockIdx.y * 32;
#pragma unroll
    for (int j = 0; j < 32; j += 8)
        t[ty + j][tx] = W[(size_t)(by + ty + j) * QKV_N + bx + tx];
    __syncthreads();
#pragma unroll
    for (int j = 0; j < 32; j += 8) {
        float v = t[tx][ty + j];
        __half h = __float2half(v);
        size_t o = (size_t)(bx + ty + j) * C_DIM + by + tx;
        g_WThi[o] = h;
        g_WTlo[o] = __float2half(v - __half2float(h));
    }
}

// q/k: add bias, split to fp16 hi/lo.  One thread = 2 elements.
__global__ void __launch_bounds__(256) bias_split_qk(const float* __restrict__ bias) {
    size_t i = ((size_t)blockIdx.x * 256 + threadIdx.x) * 2;   // over T * 2NF
    int t = (int)(i / (2 * NF_DIM));
    int c = (int)(i % (2 * NF_DIM));
    const float* src = g_qkv + (size_t)t * QKV_N + c;
    float v0 = src[0] + bias[c];
    float v1 = src[1] + bias[c + 1];
    __half h0 = __float2half(v0), h1 = __float2half(v1);
    __half l0 = __float2half(v0 - __half2float(h0));
    __half l1 = __float2half(v1 - __half2float(h1));
    __half* dh;
    __half* dl;
    int col = c;
    if (c < NF_DIM) { dh = g_qhi; dl = g_qlo; }
    else            { dh = g_khi; dl = g_klo; col = c - NF_DIM; }
    size_t o = (size_t)t * NF_DIM + col;
    *(__half2*)(dh + o) = __halves2half2(h0, h1);
    *(__half2*)(dl + o) = __halves2half2(l0, l1);
}

// v^T: read v block of g_qkv (+bias), transpose, split.
__global__ void __launch_bounds__(256) transpose_split_v(const float* __restrict__ bias) {
    __shared__ float t[32][33];
    const int tx = threadIdx.x, ty = threadIdx.y;  // 32 x 8
    const int bx = blockIdx.x * 32;   // over NF (v col)
    const int by = blockIdx.y * 32;   // over T
#pragma unroll
    for (int j = 0; j < 32; j += 8)
        t[ty + j][tx] = g_qkv[(size_t)(by + ty + j) * QKV_N + 2 * NF_DIM + bx + tx]
                        + bias[2 * NF_DIM + bx + tx];
    __syncthreads();
#pragma unroll
    for (int j = 0; j < 32; j += 8) {
        float v = t[tx][ty + j];
        __half h = __float2half(v);
        size_t o = (size_t)(bx + ty + j) * T_DIM + by + tx;
        g_vThi[o] = h;
        g_vTlo[o] = __float2half(v - __half2float(h));
    }
}

// ---------------------------------------------------------------------------
// Softmax (scale folded): p = softmax(att*scale) -> fp16 hi/lo
// ---------------------------------------------------------------------------
__global__ void __launch_bounds__(256) softmax_kernel(const int* __restrict__ npadd_ptr) {
    const int i = blockIdx.x;
    const int tid = threadIdx.x;
    const int np = *npadd_ptr;
    const float scale = 0.02209708691207961f;  // 1/sqrt(2048)
    const float* row = g_att + (size_t)i * T_DIM;
    __half* ph = g_phi + (size_t)i * T_DIM;
    __half* pl = g_plo + (size_t)i * T_DIM;
    __shared__ float red[256];

    if (i < np) {
        const __half z = __float2half(0.f);
        for (int j = tid; j < T_DIM; j += 256) { ph[j] = z; pl[j] = z; }
        return;
    }

    float m = -3.402823466e+38f;
    for (int j = np + tid; j <= i; j += 256) m = fmaxf(m, row[j] * scale);
    red[tid] = m;
    __syncthreads();
    for (int s = 128; s > 0; s >>= 1) {
        if (tid < s) red[tid] = fmaxf(red[tid], red[tid + s]);
        __syncthreads();
    }
    const float rowmax = red[0];
    __syncthreads();

    float ssum = 0.f;
    for (int j = np + tid; j <= i; j += 256) ssum += __expf(row[j] * scale - rowmax);
    red[tid] = ssum;
    __syncthreads();
    for (int s = 128; s > 0; s >>= 1) {
        if (tid < s) red[tid] += red[tid + s];
        __syncthreads();
    }
    const float inv = 1.0f / red[0];

    for (int j = tid; j < T_DIM; j += 256) {
        float pv = 0.f;
        if (j >= np && j <= i) pv = __expf(row[j] * scale - rowmax) * inv;
        __half h = __float2half(pv);
        ph[j] = h;
        pl[j] = __float2half(pv - __half2float(h));
    }
}

// ---------------------------------------------------------------------------
extern "C" void kernel_launch(void* const* d_in, const int* in_sizes, int n_in,
                              void* d_out, int out_size) {
    const float* x = (const float*)d_in[0];   // (4096, 2048)
    const float* W = (const float*)d_in[1];   // (2048, 6144)
    const float* b = (const float*)d_in[2];   // (6144,)
    const int* npad = (const int*)d_in[3];
    float* y = (float*)d_out;                 // (4096, 2048)
    (void)in_sizes; (void)n_in; (void)out_size;

    // prep
    split_x_kernel<<<(size_t)T_DIM * C_DIM / (256 * 4), 256>>>(x);
    transpose_split_W<<<dim3(QKV_N / 32, C_DIM / 32), dim3(32, 8)>>>(W);

    // raw qkv projection
    qkv_mm<<<dim3(QKV_N / 64, T_DIM / 128), 256>>>();

    // epilogues: bias+split q/k, bias+transpose+split v
    bias_split_qk<<<(size_t)T_DIM * 2 * NF_DIM / (256 * 2), 256>>>(b);
    transpose_split_v<<<dim3(NF_DIM / 32, T_DIM / 32), dim3(32, 8)>>>(b);

    // raw attention scores
    s_mm<<<dim3(T_DIM / 64, T_DIM / 128), 256>>>(npad);

    // softmax (scale folded) -> p hi/lo
    softmax_kernel<<<T_DIM, 256>>>(npad);

    // y = p @ v
    y_mm<<<dim3(NF_DIM / 64, T_DIM / 128), 256>>>(y, npad);
}

// round 13
// speedup vs baseline: 2.4713x; 1.1152x over previous
#include <cuda_runtime.h>
#include <cuda_fp16.h>
#include <mma.h>
#include <stdint.h>

using namespace nvcuda;

#define T_DIM 4096
#define C_DIM 2048
#define NF_DIM 2048
#define QKV_N 6144
#define SA 40                       // SMEM row stride (halves)
#define SMEM_GEMM_BYTES 81920       // 8 * 128 * SA * 2

// smem half-offsets: A[buf][hl] then B[buf][hl], each 128 x SA
#define AOFF(buf, hl) ((((buf)*2 + (hl)) * 128) * SA)
#define BOFF(buf, hl) (4 * 128 * SA + (((buf)*2 + (hl)) * 128) * SA)

// ---------------------------------------------------------------------------
// Scratch (__device__ globals; allocation-free rule)
// ---------------------------------------------------------------------------
__device__ float g_att[(size_t)T_DIM * T_DIM];        // raw scores (unscaled)
__device__ __half g_xhi[(size_t)T_DIM * C_DIM];
__device__ __half g_xlo[(size_t)T_DIM * C_DIM];
__device__ __half g_WThi[(size_t)QKV_N * C_DIM];      // W^T : [6144][2048]
__device__ __half g_WTlo[(size_t)QKV_N * C_DIM];
__device__ __half g_qhi[(size_t)T_DIM * NF_DIM];
__device__ __half g_qlo[(size_t)T_DIM * NF_DIM];
__device__ __half g_khi[(size_t)T_DIM * NF_DIM];
__device__ __half g_klo[(size_t)T_DIM * NF_DIM];
__device__ __half g_vThi[(size_t)NF_DIM * T_DIM];     // v^T : [2048][4096]
__device__ __half g_vTlo[(size_t)NF_DIM * T_DIM];
__device__ __half g_phi[(size_t)T_DIM * T_DIM];
__device__ __half g_plo[(size_t)T_DIM * T_DIM];

typedef wmma::fragment<wmma::accumulator, 16, 16, 16, float> AccFrag;
typedef wmma::fragment<wmma::matrix_a, 16, 16, 16, __half, wmma::row_major> AFrag;
typedef wmma::fragment<wmma::matrix_b, 16, 16, 16, __half, wmma::col_major> BFrag;

__device__ __forceinline__ uint32_t smem_to_u32(const void* p) {
    uint32_t a;
    asm("{ .reg .u64 t; cvta.to.shared.u64 t, %1; cvt.u32.u64 %0, t; }" : "=r"(a) : "l"(p));
    return a;
}

#define CP16(dst_u32, src_ptr) \
    asm volatile("cp.async.cg.shared.global [%0], [%1], 16;" \
                 :: "r"(dst_u32), "l"(src_ptr))
#define CP_COMMIT() asm volatile("cp.async.commit_group;")
#define CP_WAIT1()  asm volatile("cp.async.wait_group 1;")
#define CP_WAIT0()  asm volatile("cp.async.wait_group 0;")

// ---------------------------------------------------------------------------
// Async-load one k32 chunk of A(128 rows) and B(128 rows) hi+lo into buf.
// 8 cp.async of 16B per thread.
// ---------------------------------------------------------------------------
__device__ __forceinline__ void load_chunk_async(
    uint32_t smu,
    const __half* __restrict__ Ahi, const __half* __restrict__ Alo, int m0, int lda,
    const __half* __restrict__ Bhi, const __half* __restrict__ Blo, int n0, int ldb,
    int kc, int buf, int tid)
{
    const int row = tid >> 1;
    const int seg = (tid & 1) * 16;   // halves (32B)
    {
        const __half* s0 = Ahi + (size_t)(m0 + row) * lda + kc + seg;
        const __half* s1 = Alo + (size_t)(m0 + row) * lda + kc + seg;
        uint32_t d0 = smu + (uint32_t)(AOFF(buf, 0) + row * SA + seg) * 2;
        uint32_t d1 = smu + (uint32_t)(AOFF(buf, 1) + row * SA + seg) * 2;
        CP16(d0, s0); CP16(d0 + 16, s0 + 8);
        CP16(d1, s1); CP16(d1 + 16, s1 + 8);
    }
    {
        const __half* s0 = Bhi + (size_t)(n0 + row) * ldb + kc + seg;
        const __half* s1 = Blo + (size_t)(n0 + row) * ldb + kc + seg;
        uint32_t d0 = smu + (uint32_t)(BOFF(buf, 0) + row * SA + seg) * 2;
        uint32_t d1 = smu + (uint32_t)(BOFF(buf, 1) + row * SA + seg) * 2;
        CP16(d0, s0); CP16(d0 + 16, s0 + 8);
        CP16(d1, s1); CP16(d1 + 16, s1 + 8);
    }
}

// ---------------------------------------------------------------------------
// Compute one k32 chunk: warp tile 64x32 (4x2 wmma frags), 3-pass hi/lo.
// ---------------------------------------------------------------------------
__device__ __forceinline__ void compute_chunk(const __half* sm, int buf,
                                              int warp_m, int warp_n,
                                              AccFrag acc[4][2])
{
#pragma unroll
    for (int ks = 0; ks < 32; ks += 16) {
        BFrag bh[2], bl[2];
#pragma unroll
        for (int nt = 0; nt < 2; nt++) {
            wmma::load_matrix_sync(bh[nt], sm + BOFF(buf, 0) + (warp_n + nt * 16) * SA + ks, SA);
            wmma::load_matrix_sync(bl[nt], sm + BOFF(buf, 1) + (warp_n + nt * 16) * SA + ks, SA);
        }
#pragma unroll
        for (int mt = 0; mt < 4; mt++) {
            AFrag ah, al;
            wmma::load_matrix_sync(ah, sm + AOFF(buf, 0) + (warp_m + mt * 16) * SA + ks, SA);
            wmma::load_matrix_sync(al, sm + AOFF(buf, 1) + (warp_m + mt * 16) * SA + ks, SA);
#pragma unroll
            for (int nt = 0; nt < 2; nt++) {
                wmma::mma_sync(acc[mt][nt], ah, bh[nt], acc[mt][nt]);
                wmma::mma_sync(acc[mt][nt], ah, bl[nt], acc[mt][nt]);
                wmma::mma_sync(acc[mt][nt], al, bh[nt], acc[mt][nt]);
            }
        }
    }
}

// ---------------------------------------------------------------------------
// Full double-buffered mainloop. 256 threads, warp grid 2(m) x 4(n).
// ---------------------------------------------------------------------------
__device__ __forceinline__ void mm_main(
    __half* sm,
    const __half* __restrict__ Ahi, const __half* __restrict__ Alo, int m0, int lda,
    const __half* __restrict__ Bhi, const __half* __restrict__ Blo, int n0, int ldb,
    int kstart, int kend, AccFrag acc[4][2])
{
    const int tid = threadIdx.x;
    const int wid = tid >> 5;
    const int warp_m = (wid >> 2) * 64;
    const int warp_n = (wid & 3) * 32;
    uint32_t smu = smem_to_u32(sm);

    load_chunk_async(smu, Ahi, Alo, m0, lda, Bhi, Blo, n0, ldb, kstart, 0, tid);
    CP_COMMIT();
    int buf = 0;
    for (int kc = kstart; kc < kend; kc += 32) {
        if (kc + 32 < kend) {
            load_chunk_async(smu, Ahi, Alo, m0, lda, Bhi, Blo, n0, ldb, kc + 32, buf ^ 1, tid);
            CP_COMMIT();
            CP_WAIT1();
        } else {
            CP_WAIT0();
        }
        __syncthreads();
        compute_chunk(sm, buf, warp_m, warp_n, acc);
        __syncthreads();
        buf ^= 1;
    }
}

__device__ __forceinline__ void acc_zero(AccFrag acc[4][2]) {
#pragma unroll
    for (int mt = 0; mt < 4; mt++)
#pragma unroll
        for (int nt = 0; nt < 2; nt++) wmma::fill_fragment(acc[mt][nt], 0.f);
}

// ---------------------------------------------------------------------------
// GEMM 1: qkv = x @ W + b, fused epilogue:
//   q,k -> fp16 hi/lo row-major;  v -> fp16 hi/lo TRANSPOSED (v^T).
// ---------------------------------------------------------------------------
__global__ void __launch_bounds__(256) qkv_mm(const float* __restrict__ bias) {
    extern __shared__ __half sm[];
    AccFrag acc[4][2];
    acc_zero(acc);
    const int m0 = blockIdx.y * 128, n0 = blockIdx.x * 128;
    mm_main(sm, g_xhi, g_xlo, m0, C_DIM, g_WThi, g_WTlo, n0, C_DIM, 0, C_DIM, acc);

    // stage accumulators to SMEM (fp32, 128x128)
    float* stg = (float*)sm;
    const int wid = threadIdx.x >> 5;
    const int warp_m = (wid >> 2) * 64, warp_n = (wid & 3) * 32;
#pragma unroll
    for (int mt = 0; mt < 4; mt++)
#pragma unroll
        for (int nt = 0; nt < 2; nt++)
            wmma::store_matrix_sync(stg + (warp_m + mt * 16) * 128 + warp_n + nt * 16,
                                    acc[mt][nt], 128, wmma::mem_row_major);
    __syncthreads();

    const int tid = threadIdx.x;
    if (n0 < 2 * NF_DIM) {
        // q or k: row-major hi/lo with bias
        __half* dh;
        __half* dl;
        int colbase;
        if (n0 < NF_DIM) { dh = g_qhi; dl = g_qlo; colbase = n0; }
        else             { dh = g_khi; dl = g_klo; colbase = n0 - NF_DIM; }
        for (int e = tid; e < 128 * 64; e += 256) {
            int r = e >> 6, c2 = (e & 63) * 2;
            float v0 = stg[r * 128 + c2]     + bias[n0 + c2];
            float v1 = stg[r * 128 + c2 + 1] + bias[n0 + c2 + 1];
            __half h0 = __float2half(v0), h1 = __float2half(v1);
            __half l0 = __float2half(v0 - __half2float(h0));
            __half l1 = __float2half(v1 - __half2float(h1));
            size_t o = (size_t)(m0 + r) * NF_DIM + colbase + c2;
            *(__half2*)(dh + o) = __halves2half2(h0, h1);
            *(__half2*)(dl + o) = __halves2half2(l0, l1);
        }
    } else {
        // v: transposed hi/lo with bias -> g_vT[col][t]
        for (int e = tid; e < 128 * 128; e += 256) {
            int c = e >> 7, r = e & 127;
            float v = stg[r * 128 + c] + bias[n0 + c];
            __half h = __float2half(v);
            size_t o = (size_t)(n0 - 2 * NF_DIM + c) * T_DIM + m0 + r;
            g_vThi[o] = h;
            g_vTlo[o] = __float2half(v - __half2float(h));
        }
    }
}

// ---------------------------------------------------------------------------
// GEMM 2: raw att = q @ k^T  (scale folded into softmax)
// ---------------------------------------------------------------------------
__global__ void __launch_bounds__(256) s_mm(const int* __restrict__ npadd_ptr) {
    const int ib = blockIdx.y, jb = blockIdx.x;
    if (jb > ib) return;                       // fully above diagonal
    const int np = *npadd_ptr;
    if ((jb + 1) * 128 <= np) return;          // all cols padded
    if ((ib + 1) * 128 <= np) return;          // all rows padded

    extern __shared__ __half sm[];
    AccFrag acc[4][2];
    acc_zero(acc);
    const int m0 = ib * 128, n0 = jb * 128;
    mm_main(sm, g_qhi, g_qlo, m0, NF_DIM, g_khi, g_klo, n0, NF_DIM, 0, NF_DIM, acc);

    const int wid = threadIdx.x >> 5;
    const int warp_m = (wid >> 2) * 64, warp_n = (wid & 3) * 32;
#pragma unroll
    for (int mt = 0; mt < 4; mt++)
#pragma unroll
        for (int nt = 0; nt < 2; nt++)
            wmma::store_matrix_sync(
                g_att + (size_t)(m0 + warp_m + mt * 16) * T_DIM + n0 + warp_n + nt * 16,
                acc[mt][nt], T_DIM, wmma::mem_row_major);
}

// ---------------------------------------------------------------------------
// GEMM 3: y = p @ v  (K truncated at diagonal / padding), store direct to out.
// ---------------------------------------------------------------------------
__global__ void __launch_bounds__(256) y_mm(float* __restrict__ Y,
                                            const int* __restrict__ npadd_ptr) {
    const int ib = blockIdx.y;
    const int m0 = ib * 128, n0 = blockIdx.x * 128;
    const int np = *npadd_ptr;
    const int kstart = np & ~31;
    const int kend = (ib + 1) * 128;

    if (kstart >= kend) {  // fully padded row block -> zeros
        const int tid = threadIdx.x;
        for (int e = tid; e < 128 * 32; e += 256) {
            int r = e >> 5, c4 = (e & 31) * 4;
            *(float4*)&Y[(size_t)(m0 + r) * NF_DIM + n0 + c4] =
                make_float4(0.f, 0.f, 0.f, 0.f);
        }
        return;
    }

    extern __shared__ __half sm[];
    AccFrag acc[4][2];
    acc_zero(acc);
    mm_main(sm, g_phi, g_plo, m0, T_DIM, g_vThi, g_vTlo, n0, T_DIM, kstart, kend, acc);

    const int wid = threadIdx.x >> 5;
    const int warp_m = (wid >> 2) * 64, warp_n = (wid & 3) * 32;
#pragma unroll
    for (int mt = 0; mt < 4; mt++)
#pragma unroll
        for (int nt = 0; nt < 2; nt++)
            wmma::store_matrix_sync(
                Y + (size_t)(m0 + warp_m + mt * 16) * NF_DIM + n0 + warp_n + nt * 16,
                acc[mt][nt], NF_DIM, wmma::mem_row_major);
}

// ---------------------------------------------------------------------------
// Prep kernels
// ---------------------------------------------------------------------------
__global__ void __launch_bounds__(256) split_x_kernel(const float* __restrict__ x) {
    size_t i = ((size_t)blockIdx.x * 256 + threadIdx.x) * 4;
    float4 v = *(const float4*)(x + i);
    float f[4] = {v.x, v.y, v.z, v.w};
    __half h[4], l[4];
#pragma unroll
    for (int e = 0; e < 4; e++) {
        h[e] = __float2half(f[e]);
        l[e] = __float2half(f[e] - __half2float(h[e]));
    }
    *(uint2*)(g_xhi + i) = *(const uint2*)h;
    *(uint2*)(g_xlo + i) = *(const uint2*)l;
}

// W^T split: dst[col][row] = split(W[row][col])
__global__ void __launch_bounds__(256) transpose_split_W(const float* __restrict__ W) {
    __shared__ float t[32][33];
    const int tx = threadIdx.x, ty = threadIdx.y;  // 32 x 8
    const int bx = blockIdx.x * 32, by = blockIdx.y * 32;
#pragma unroll
    for (int j = 0; j < 32; j += 8)
        t[ty + j][tx] = W[(size_t)(by + ty + j) * QKV_N + bx + tx];
    __syncthreads();
#pragma unroll
    for (int j = 0; j < 32; j += 8) {
        float v = t[tx][ty + j];
        __half h = __float2half(v);
        size_t o = (size_t)(bx + ty + j) * C_DIM + by + tx;
        g_WThi[o] = h;
        g_WTlo[o] = __float2half(v - __half2float(h));
    }
}

// ---------------------------------------------------------------------------
// Softmax (scale folded): p = softmax(att*scale) -> fp16 hi/lo
// ---------------------------------------------------------------------------
__global__ void __launch_bounds__(256) softmax_kernel(const int* __restrict__ npadd_ptr) {
    const int i = blockIdx.x;
    const int tid = threadIdx.x;
    const int np = *npadd_ptr;
    const float scale = 0.02209708691207961f;  // 1/sqrt(2048)
    const float* row = g_att + (size_t)i * T_DIM;
    __half* ph = g_phi + (size_t)i * T_DIM;
    __half* pl = g_plo + (size_t)i * T_DIM;
    __shared__ float red[256];

    if (i < np) {
        const __half z = __float2half(0.f);
        for (int j = tid; j < T_DIM; j += 256) { ph[j] = z; pl[j] = z; }
        return;
    }

    float m = -3.402823466e+38f;
    for (int j = np + tid; j <= i; j += 256) m = fmaxf(m, row[j] * scale);
    red[tid] = m;
    __syncthreads();
    for (int s = 128; s > 0; s >>= 1) {
        if (tid < s) red[tid] = fmaxf(red[tid], red[tid + s]);
        __syncthreads();
    }
    const float rowmax = red[0];
    __syncthreads();

    float ssum = 0.f;
    for (int j = np + tid; j <= i; j += 256) ssum += __expf(row[j] * scale - rowmax);
    red[tid] = ssum;
    __syncthreads();
    for (int s = 128; s > 0; s >>= 1) {
        if (tid < s) red[tid] += red[tid + s];
        __syncthreads();
    }
    const float inv = 1.0f / red[0];

    for (int j = tid; j < T_DIM; j += 256) {
        float pv = 0.f;
        if (j >= np && j <= i) pv = __expf(row[j] * scale - rowmax) * inv;
        __half h = __float2half(pv);
        ph[j] = h;
        pl[j] = __float2half(pv - __half2float(h));
    }
}

// ---------------------------------------------------------------------------
extern "C" void kernel_launch(void* const* d_in, const int* in_sizes, int n_in,
                              void* d_out, int out_size) {
    const float* x = (const float*)d_in[0];   // (4096, 2048)
    const float* W = (const float*)d_in[1];   // (2048, 6144)
    const float* b = (const float*)d_in[2];   // (6144,)
    const int* npad = (const int*)d_in[3];
    float* y = (float*)d_out;                 // (4096, 2048)
    (void)in_sizes; (void)n_in; (void)out_size;

    cudaFuncSetAttribute(qkv_mm, cudaFuncAttributeMaxDynamicSharedMemorySize, SMEM_GEMM_BYTES);
    cudaFuncSetAttribute(s_mm, cudaFuncAttributeMaxDynamicSharedMemorySize, SMEM_GEMM_BYTES);
    cudaFuncSetAttribute(y_mm, cudaFuncAttributeMaxDynamicSharedMemorySize, SMEM_GEMM_BYTES);

    // prep
    split_x_kernel<<<(size_t)T_DIM * C_DIM / (256 * 4), 256>>>(x);
    transpose_split_W<<<dim3(QKV_N / 32, C_DIM / 32), dim3(32, 8)>>>(W);

    // qkv projection (fused bias + split + v-transpose epilogue)
    qkv_mm<<<dim3(QKV_N / 128, T_DIM / 128), 256, SMEM_GEMM_BYTES>>>(b);

    // raw attention scores
    s_mm<<<dim3(T_DIM / 128, T_DIM / 128), 256, SMEM_GEMM_BYTES>>>(npad);

    // softmax (scale folded) -> p hi/lo
    softmax_kernel<<<T_DIM, 256>>>(npad);

    // y = p @ v
    y_mm<<<dim3(NF_DIM / 128, T_DIM / 128), 256, SMEM_GEMM_BYTES>>>(y, npad);
}

// round 16
// speedup vs baseline: 2.4855x; 1.0058x over previous
#include <cuda_runtime.h>
#include <cuda_fp16.h>
#include <mma.h>
#include <stdint.h>

using namespace nvcuda;

#define T_DIM 4096
#define C_DIM 2048
#define NF_DIM 2048
#define QKV_N 6144
#define SA 40                       // SMEM row stride (halves)
#define SMEM_GEMM_BYTES 81920       // 8 * 128 * SA * 2

// smem half-offsets: A[buf][hl] then B[buf][hl], each 128 x SA
#define AOFF(buf, hl) ((((buf)*2 + (hl)) * 128) * SA)
#define BOFF(buf, hl) (4 * 128 * SA + (((buf)*2 + (hl)) * 128) * SA)

// ---------------------------------------------------------------------------
// Scratch (__device__ globals; allocation-free rule)
// ---------------------------------------------------------------------------
__device__ float g_att[(size_t)T_DIM * T_DIM];        // raw scores (unscaled)
__device__ __half g_xhi[(size_t)T_DIM * C_DIM];
__device__ __half g_xlo[(size_t)T_DIM * C_DIM];
__device__ __half g_WThi[(size_t)QKV_N * C_DIM];      // W^T : [6144][2048]
__device__ __half g_WTlo[(size_t)QKV_N * C_DIM];
__device__ __half g_qhi[(size_t)T_DIM * NF_DIM];
__device__ __half g_qlo[(size_t)T_DIM * NF_DIM];
__device__ __half g_khi[(size_t)T_DIM * NF_DIM];
__device__ __half g_klo[(size_t)T_DIM * NF_DIM];
__device__ __half g_vThi[(size_t)NF_DIM * T_DIM];     // v^T : [2048][4096]
__device__ __half g_vTlo[(size_t)NF_DIM * T_DIM];
__device__ __half g_phi[(size_t)T_DIM * T_DIM];
__device__ __half g_plo[(size_t)T_DIM * T_DIM];

typedef wmma::fragment<wmma::accumulator, 16, 16, 16, float> AccFrag;
typedef wmma::fragment<wmma::matrix_a, 16, 16, 16, __half, wmma::row_major> AFrag;
typedef wmma::fragment<wmma::matrix_b, 16, 16, 16, __half, wmma::col_major> BFrag;

__device__ __forceinline__ uint32_t smem_to_u32(const void* p) {
    uint32_t a;
    asm("{ .reg .u64 t; cvta.to.shared.u64 t, %1; cvt.u32.u64 %0, t; }" : "=r"(a) : "l"(p));
    return a;
}

#define CP16(dst_u32, src_ptr) \
    asm volatile("cp.async.cg.shared.global [%0], [%1], 16;" \
                 :: "r"(dst_u32), "l"(src_ptr))
#define CP_COMMIT() asm volatile("cp.async.commit_group;")
#define CP_WAIT1()  asm volatile("cp.async.wait_group 1;")
#define CP_WAIT0()  asm volatile("cp.async.wait_group 0;")

// ---------------------------------------------------------------------------
// Async-load one k32 chunk of A(128 rows) and B(128 rows) hi+lo into buf.
// ---------------------------------------------------------------------------
__device__ __forceinline__ void load_chunk_async(
    uint32_t smu,
    const __half* __restrict__ Ahi, const __half* __restrict__ Alo, int m0, int lda,
    const __half* __restrict__ Bhi, const __half* __restrict__ Blo, int n0, int ldb,
    int kc, int buf, int tid)
{
    const int row = tid >> 1;
    const int seg = (tid & 1) * 16;   // halves (32B)
    {
        const __half* s0 = Ahi + (size_t)(m0 + row) * lda + kc + seg;
        const __half* s1 = Alo + (size_t)(m0 + row) * lda + kc + seg;
        uint32_t d0 = smu + (uint32_t)(AOFF(buf, 0) + row * SA + seg) * 2;
        uint32_t d1 = smu + (uint32_t)(AOFF(buf, 1) + row * SA + seg) * 2;
        CP16(d0, s0); CP16(d0 + 16, s0 + 8);
        CP16(d1, s1); CP16(d1 + 16, s1 + 8);
    }
    {
        const __half* s0 = Bhi + (size_t)(n0 + row) * ldb + kc + seg;
        const __half* s1 = Blo + (size_t)(n0 + row) * ldb + kc + seg;
        uint32_t d0 = smu + (uint32_t)(BOFF(buf, 0) + row * SA + seg) * 2;
        uint32_t d1 = smu + (uint32_t)(BOFF(buf, 1) + row * SA + seg) * 2;
        CP16(d0, s0); CP16(d0 + 16, s0 + 8);
        CP16(d1, s1); CP16(d1 + 16, s1 + 8);
    }
}

// ---------------------------------------------------------------------------
// Compute one k32 chunk: warp tile 64x32 (4x2 wmma frags), 3-pass hi/lo.
// MMAs interleaved across nt so each accumulator's dependency distance is 2
// wmma (= 4 HMMA) instead of 1 — doubles per-warp tensor-pipe ILP.
// ---------------------------------------------------------------------------
__device__ __forceinline__ void compute_chunk(const __half* sm, int buf,
                                              int warp_m, int warp_n,
                                              AccFrag acc[4][2])
{
#pragma unroll
    for (int ks = 0; ks < 32; ks += 16) {
        BFrag bh[2], bl[2];
#pragma unroll
        for (int nt = 0; nt < 2; nt++) {
            wmma::load_matrix_sync(bh[nt], sm + BOFF(buf, 0) + (warp_n + nt * 16) * SA + ks, SA);
            wmma::load_matrix_sync(bl[nt], sm + BOFF(buf, 1) + (warp_n + nt * 16) * SA + ks, SA);
        }
#pragma unroll
        for (int mt = 0; mt < 4; mt++) {
            AFrag ah, al;
            wmma::load_matrix_sync(ah, sm + AOFF(buf, 0) + (warp_m + mt * 16) * SA + ks, SA);
            wmma::load_matrix_sync(al, sm + AOFF(buf, 1) + (warp_m + mt * 16) * SA + ks, SA);
            // distance-2 interleave over nt
            wmma::mma_sync(acc[mt][0], ah, bh[0], acc[mt][0]);
            wmma::mma_sync(acc[mt][1], ah, bh[1], acc[mt][1]);
            wmma::mma_sync(acc[mt][0], ah, bl[0], acc[mt][0]);
            wmma::mma_sync(acc[mt][1], ah, bl[1], acc[mt][1]);
            wmma::mma_sync(acc[mt][0], al, bh[0], acc[mt][0]);
            wmma::mma_sync(acc[mt][1], al, bh[1], acc[mt][1]);
        }
    }
}

// ---------------------------------------------------------------------------
// Full double-buffered mainloop. 256 threads, warp grid 2(m) x 4(n).
// ---------------------------------------------------------------------------
__device__ __forceinline__ void mm_main(
    __half* sm,
    const __half* __restrict__ Ahi, const __half* __restrict__ Alo, int m0, int lda,
    const __half* __restrict__ Bhi, const __half* __restrict__ Blo, int n0, int ldb,
    int kstart, int kend, AccFrag acc[4][2])
{
    const int tid = threadIdx.x;
    const int wid = tid >> 5;
    const int warp_m = (wid >> 2) * 64;
    const int warp_n = (wid & 3) * 32;
    uint32_t smu = smem_to_u32(sm);

    load_chunk_async(smu, Ahi, Alo, m0, lda, Bhi, Blo, n0, ldb, kstart, 0, tid);
    CP_COMMIT();
    int buf = 0;
    for (int kc = kstart; kc < kend; kc += 32) {
        if (kc + 32 < kend) {
            load_chunk_async(smu, Ahi, Alo, m0, lda, Bhi, Blo, n0, ldb, kc + 32, buf ^ 1, tid);
            CP_COMMIT();
            CP_WAIT1();
        } else {
            CP_WAIT0();
        }
        __syncthreads();
        compute_chunk(sm, buf, warp_m, warp_n, acc);
        __syncthreads();
        buf ^= 1;
    }
}

__device__ __forceinline__ void acc_zero(AccFrag acc[4][2]) {
#pragma unroll
    for (int mt = 0; mt < 4; mt++)
#pragma unroll
        for (int nt = 0; nt < 2; nt++) wmma::fill_fragment(acc[mt][nt], 0.f);
}

// ---------------------------------------------------------------------------
// GEMM 1: qkv = x @ W + b, fused epilogue:
//   q,k -> fp16 hi/lo row-major;  v -> fp16 hi/lo TRANSPOSED (v^T).
// ---------------------------------------------------------------------------
__global__ void __launch_bounds__(256, 2) qkv_mm(const float* __restrict__ bias) {
    extern __shared__ __half sm[];
    AccFrag acc[4][2];
    acc_zero(acc);
    const int m0 = blockIdx.y * 128, n0 = blockIdx.x * 128;
    mm_main(sm, g_xhi, g_xlo, m0, C_DIM, g_WThi, g_WTlo, n0, C_DIM, 0, C_DIM, acc);

    // stage accumulators to SMEM (fp32, 128x128)
    float* stg = (float*)sm;
    const int wid = threadIdx.x >> 5;
    const int warp_m = (wid >> 2) * 64, warp_n = (wid & 3) * 32;
#pragma unroll
    for (int mt = 0; mt < 4; mt++)
#pragma unroll
        for (int nt = 0; nt < 2; nt++)
            wmma::store_matrix_sync(stg + (warp_m + mt * 16) * 128 + warp_n + nt * 16,
                                    acc[mt][nt], 128, wmma::mem_row_major);
    __syncthreads();

    const int tid = threadIdx.x;
    if (n0 < 2 * NF_DIM) {
        // q or k: row-major hi/lo with bias
        __half* dh;
        __half* dl;
        int colbase;
        if (n0 < NF_DIM) { dh = g_qhi; dl = g_qlo; colbase = n0; }
        else             { dh = g_khi; dl = g_klo; colbase = n0 - NF_DIM; }
        for (int e = tid; e < 128 * 64; e += 256) {
            int r = e >> 6, c2 = (e & 63) * 2;
            float v0 = stg[r * 128 + c2]     + bias[n0 + c2];
            float v1 = stg[r * 128 + c2 + 1] + bias[n0 + c2 + 1];
            __half h0 = __float2half(v0), h1 = __float2half(v1);
            __half l0 = __float2half(v0 - __half2float(h0));
            __half l1 = __float2half(v1 - __half2float(h1));
            size_t o = (size_t)(m0 + r) * NF_DIM + colbase + c2;
            *(__half2*)(dh + o) = __halves2half2(h0, h1);
            *(__half2*)(dl + o) = __halves2half2(l0, l1);
        }
    } else {
        // v: transposed hi/lo with bias -> g_vT[col][t]
        for (int e = tid; e < 128 * 128; e += 256) {
            int c = e >> 7, r = e & 127;
            float v = stg[r * 128 + c] + bias[n0 + c];
            __half h = __float2half(v);
            size_t o = (size_t)(n0 - 2 * NF_DIM + c) * T_DIM + m0 + r;
            g_vThi[o] = h;
            g_vTlo[o] = __float2half(v - __half2float(h));
        }
    }
}

// ---------------------------------------------------------------------------
// GEMM 2: raw att = q @ k^T  (scale folded into softmax)
// ---------------------------------------------------------------------------
__global__ void __launch_bounds__(256, 2) s_mm(const int* __restrict__ npadd_ptr) {
    const int ib = blockIdx.y, jb = blockIdx.x;
    if (jb > ib) return;                       // fully above diagonal
    const int np = *npadd_ptr;
    if ((jb + 1) * 128 <= np) return;          // all cols padded
    if ((ib + 1) * 128 <= np) return;          // all rows padded

    extern __shared__ __half sm[];
    AccFrag acc[4][2];
    acc_zero(acc);
    const int m0 = ib * 128, n0 = jb * 128;
    mm_main(sm, g_qhi, g_qlo, m0, NF_DIM, g_khi, g_klo, n0, NF_DIM, 0, NF_DIM, acc);

    const int wid = threadIdx.x >> 5;
    const int warp_m = (wid >> 2) * 64, warp_n = (wid & 3) * 32;
#pragma unroll
    for (int mt = 0; mt < 4; mt++)
#pragma unroll
        for (int nt = 0; nt < 2; nt++)
            wmma::store_matrix_sync(
                g_att + (size_t)(m0 + warp_m + mt * 16) * T_DIM + n0 + warp_n + nt * 16,
                acc[mt][nt], T_DIM, wmma::mem_row_major);
}

// ---------------------------------------------------------------------------
// GEMM 3: y = p @ v  (K truncated at diagonal / padding), store direct to out.
// ---------------------------------------------------------------------------
__global__ void __launch_bounds__(256, 2) y_mm(float* __restrict__ Y,
                                               const int* __restrict__ npadd_ptr) {
    const int ib = blockIdx.y;
    const int m0 = ib * 128, n0 = blockIdx.x * 128;
    const int np = *npadd_ptr;
    const int kstart = np & ~31;
    const int kend = (ib + 1) * 128;

    if (kstart >= kend) {  // fully padded row block -> zeros
        const int tid = threadIdx.x;
        for (int e = tid; e < 128 * 32; e += 256) {
            int r = e >> 5, c4 = (e & 31) * 4;
            *(float4*)&Y[(size_t)(m0 + r) * NF_DIM + n0 + c4] =
                make_float4(0.f, 0.f, 0.f, 0.f);
        }
        return;
    }

    extern __shared__ __half sm[];
    AccFrag acc[4][2];
    acc_zero(acc);
    mm_main(sm, g_phi, g_plo, m0, T_DIM, g_vThi, g_vTlo, n0, T_DIM, kstart, kend, acc);

    const int wid = threadIdx.x >> 5;
    const int warp_m = (wid >> 2) * 64, warp_n = (wid & 3) * 32;
#pragma unroll
    for (int mt = 0; mt < 4; mt++)
#pragma unroll
        for (int nt = 0; nt < 2; nt++)
            wmma::store_matrix_sync(
                Y + (size_t)(m0 + warp_m + mt * 16) * NF_DIM + n0 + warp_n + nt * 16,
                acc[mt][nt], NF_DIM, wmma::mem_row_major);
}

// ---------------------------------------------------------------------------
// Prep kernels
// ---------------------------------------------------------------------------
__global__ void __launch_bounds__(256) split_x_kernel(const float* __restrict__ x) {
    size_t i = ((size_t)blockIdx.x * 256 + threadIdx.x) * 4;
    float4 v = *(const float4*)(x + i);
    float f[4] = {v.x, v.y, v.z, v.w};
    __half h[4], l[4];
#pragma unroll
    for (int e = 0; e < 4; e++) {
        h[e] = __float2half(f[e]);
        l[e] = __float2half(f[e] - __half2float(h[e]));
    }
    *(uint2*)(g_xhi + i) = *(const uint2*)h;
    *(uint2*)(g_xlo + i) = *(const uint2*)l;
}

// W^T split: dst[col][row] = split(W[row][col])
__global__ void __launch_bounds__(256) transpose_split_W(const float* __restrict__ W) {
    __shared__ float t[32][33];
    const int tx = threadIdx.x, ty = threadIdx.y;  // 32 x 8
    const int bx = blockIdx.x * 32, by = blockIdx.y * 32;
#pragma unroll
    for (int j = 0; j < 32; j += 8)
        t[ty + j][tx] = W[(size_t)(by + ty + j) * QKV_N + bx + tx];
    __syncthreads();
#pragma unroll
    for (int j = 0; j < 32; j += 8) {
        float v = t[tx][ty + j];
        __half h = __float2half(v);
        size_t o = (size_t)(bx + ty + j) * C_DIM + by + tx;
        g_WThi[o] = h;
        g_WTlo[o] = __float2half(v - __half2float(h));
    }
}

// ---------------------------------------------------------------------------
// Softmax (scale folded): p = softmax(att*scale) -> fp16 hi/lo
// ---------------------------------------------------------------------------
__global__ void __launch_bounds__(256) softmax_kernel(const int* __restrict__ npadd_ptr) {
    const int i = blockIdx.x;
    const int tid = threadIdx.x;
    const int np = *npadd_ptr;
    const float scale = 0.02209708691207961f;  // 1/sqrt(2048)
    const float* row = g_att + (size_t)i * T_DIM;
    __half* ph = g_phi + (size_t)i * T_DIM;
    __half* pl = g_plo + (size_t)i * T_DIM;
    __shared__ float red[256];

    if (i < np) {
        const __half2 z2 = __halves2half2(__float2half(0.f), __float2half(0.f));
        for (int j2 = tid * 2; j2 < T_DIM; j2 += 512) {
            *(__half2*)(ph + j2) = z2;
            *(__half2*)(pl + j2) = z2;
        }
        return;
    }

    float m = -3.402823466e+38f;
    for (int j = np + tid; j <= i; j += 256) m = fmaxf(m, row[j] * scale);
    red[tid] = m;
    __syncthreads();
    for (int s = 128; s > 0; s >>= 1) {
        if (tid < s) red[tid] = fmaxf(red[tid], red[tid + s]);
        __syncthreads();
    }
    const float rowmax = red[0];
    __syncthreads();

    float ssum = 0.f;
    for (int j = np + tid; j <= i; j += 256) ssum += __expf(row[j] * scale - rowmax);
    red[tid] = ssum;
    __syncthreads();
    for (int s = 128; s > 0; s >>= 1) {
        if (tid < s) red[tid] += red[tid + s];
        __syncthreads();
    }
    const float inv = 1.0f / red[0];

    // pass 3: vectorized half2 writes
    for (int j2 = tid * 2; j2 < T_DIM; j2 += 512) {
        float pv0 = 0.f, pv1 = 0.f;
        if (j2 >= np && j2 <= i)         pv0 = __expf(row[j2] * scale - rowmax) * inv;
        if (j2 + 1 >= np && j2 + 1 <= i) pv1 = __expf(row[j2 + 1] * scale - rowmax) * inv;
        __half h0 = __float2half(pv0), h1 = __float2half(pv1);
        __half l0 = __float2half(pv0 - __half2float(h0));
        __half l1 = __float2half(pv1 - __half2float(h1));
        *(__half2*)(ph + j2) = __halves2half2(h0, h1);
        *(__half2*)(pl + j2) = __halves2half2(l0, l1);
    }
}

// ---------------------------------------------------------------------------
extern "C" void kernel_launch(void* const* d_in, const int* in_sizes, int n_in,
                              void* d_out, int out_size) {
    const float* x = (const float*)d_in[0];   // (4096, 2048)
    const float* W = (const float*)d_in[1];   // (2048, 6144)
    const float* b = (const float*)d_in[2];   // (6144,)
    const int* npad = (const int*)d_in[3];
    float* y = (float*)d_out;                 // (4096, 2048)
    (void)in_sizes; (void)n_in; (void)out_size;

    cudaFuncSetAttribute(qkv_mm, cudaFuncAttributeMaxDynamicSharedMemorySize, SMEM_GEMM_BYTES);
    cudaFuncSetAttribute(s_mm, cudaFuncAttributeMaxDynamicSharedMemorySize, SMEM_GEMM_BYTES);
    cudaFuncSetAttribute(y_mm, cudaFuncAttributeMaxDynamicSharedMemorySize, SMEM_GEMM_BYTES);

    // prep
    split_x_kernel<<<(size_t)T_DIM * C_DIM / (256 * 4), 256>>>(x);
    transpose_split_W<<<dim3(QKV_N / 32, C_DIM / 32), dim3(32, 8)>>>(W);

    // qkv projection (fused bias + split + v-transpose epilogue)
    qkv_mm<<<dim3(QKV_N / 128, T_DIM / 128), 256, SMEM_GEMM_BYTES>>>(b);

    // raw attention scores
    s_mm<<<dim3(T_DIM / 128, T_DIM / 128), 256, SMEM_GEMM_BYTES>>>(npad);

    // softmax (scale folded) -> p hi/lo
    softmax_kernel<<<T_DIM, 256>>>(npad);

    // y = p @ v
    y_mm<<<dim3(NF_DIM / 128, T_DIM / 128), 256, SMEM_GEMM_BYTES>>>(y, npad);
}